// round 16
// baseline (speedup 1.0000x reference)
#include <cuda_runtime.h>
#include <cuda_bf16.h>

#define BB   32
#define NEX  1024
#define NKC  128
#define DH   64

typedef unsigned long long u64;

// ---------------- scratch (device globals, 16B-aligned) --------------------
__device__ __align__(16) float g_x[BB * 64];
__device__ __align__(16) float g_kci2[2][BB * NKC];   // two n-half partials
__device__ __align__(16) float g_kcg[NKC * NKC];
__device__ __align__(16) float g_epart[NKC * 64];
__device__ __align__(16) float g_newh[BB * NKC * 64];
__device__ __align__(16) float g_dpart[BB * NKC * 64];
__device__ __align__(16) float g_twhhT[64 * 192];
__device__ __align__(16) float g_WdhT[64 * 64];
__device__ __align__(16) float g_ulinT[64 * 64];
__device__ __align__(16) float g_uwihT[64 * 192];
__device__ __align__(16) float g_uwhhT[64 * 192];

__device__ __forceinline__ float sigf(float v)     { return 1.f / (1.f + __expf(-v)); }
__device__ __forceinline__ float tanhfast(float v) { return 2.f / (1.f + __expf(-2.f * v)) - 1.f; }

// packed f32x2 helpers (FFMA2: 2 fp32 lanes per issue slot)
__device__ __forceinline__ u64 pack2(float x, float y) {
    u64 r; asm("mov.b64 %0, {%1, %2};" : "=l"(r) : "f"(x), "f"(y)); return r;
}
__device__ __forceinline__ void fma2(u64& acc, u64 a, u64 b) {
    asm("fma.rn.f32x2 %0, %1, %2, %0;" : "+l"(acc) : "l"(a), "l"(b));
}
__device__ __forceinline__ u64 add2(u64 a, u64 b) {
    u64 r; asm("add.rn.f32x2 %0, %1, %2;" : "=l"(r) : "l"(a), "l"(b)); return r;
}
// relu on both halves of a packed pair (scalar max.f32 on halves; movs elide)
__device__ __forceinline__ void relu2(u64& v) {
    asm("{ .reg .f32 lo, hi;\n\t"
        "mov.b64 {lo, hi}, %0;\n\t"
        "max.f32 lo, lo, 0f00000000;\n\t"
        "max.f32 hi, hi, 0f00000000;\n\t"
        "mov.b64 %0, {lo, hi}; }" : "+l"(v));
}
__device__ __forceinline__ void unpack2(u64 v, float& x, float& y) {
    asm("mov.b64 {%0, %1}, %2;" : "=f"(x), "=f"(y) : "l"(v));
}
__device__ __forceinline__ float4 up4(ulonglong2 v) {
    float4 f; unpack2(v.x, f.x, f.y); unpack2(v.y, f.z, f.w); return f;
}

// ---------------- K0: only what K2 needs, 584 blocks x 256 (R13 layout) -----
// blocks   0..511 : x      (2 warps per output, 12-load chains)
// blocks 512..575 : kci    (2 blocks per b, 8-deep load batching)
// blocks 576..583 : transposes twhhT, WdhT (16384 elems)
__global__ void __launch_bounds__(256, 1) k0(
    const float* __restrict__ ex, const float* __restrict__ su,
    const float* __restrict__ ex_graph,
    const float* __restrict__ W_ex,
    const float* __restrict__ tgru_whh,
    const float* __restrict__ fpart_w)
{
    __shared__ __align__(16) float sbuf[2176];
    int blk = blockIdx.x, tid = threadIdx.x;

    if (blk < 512) {
        int w = tid >> 5, lane = tid & 31;
        int oid = blk * 4 + (w >> 1);          // 0..2047
        int half = w & 1;
        int b = oid >> 6, e = oid & 63;
        const float4* W4  = (const float4*)W_ex + e * 512 + half * 128;
        const float4* ex4 = (const float4*)ex + b * 256 + half * 128;
        float4 ev[4], wa[4], wb[4];
        #pragma unroll
        for (int i = 0; i < 4; i++) {
            int idx = i * 32 + lane;
            ev[i] = ex4[idx];
            wa[i] = W4[idx];
            wb[i] = W4[256 + idx];
        }
        float a1 = 0.f, a2 = 0.f;
        #pragma unroll
        for (int i = 0; i < 4; i++) {
            a1 = fmaf(ev[i].x, wa[i].x, fmaf(ev[i].y, wa[i].y, fmaf(ev[i].z, wa[i].z, fmaf(ev[i].w, wa[i].w, a1))));
            a2 = fmaf(ev[i].x, wb[i].x, fmaf(ev[i].y, wb[i].y, fmaf(ev[i].z, wb[i].z, fmaf(ev[i].w, wb[i].w, a2))));
        }
        #pragma unroll
        for (int o = 16; o; o >>= 1) {
            a1 += __shfl_xor_sync(0xffffffffu, a1, o);
            a2 += __shfl_xor_sync(0xffffffffu, a2, o);
        }
        if (lane == 0) { sbuf[w * 2] = a1; sbuf[w * 2 + 1] = a2; }
        __syncthreads();
        if (tid < 4) {
            int o2 = blk * 4 + tid;
            float s1 = sbuf[tid * 4] + sbuf[tid * 4 + 2];
            float s2 = sbuf[tid * 4 + 1] + sbuf[tid * 4 + 3];
            float s = su[o2 >> 6];
            g_x[o2] = s * s1 + (1.f - s) * s2;
        }
    } else if (blk < 576) {
        int idx = blk - 512;
        int b = idx >> 1, nh = idx & 1;
        float4* exs4 = (float4*)sbuf;
        float*  red  = sbuf + 1024;
        exs4[tid] = ((const float4*)ex)[b * 256 + tid];
        __syncthreads();
        int j4 = tid & 31, ns = tid >> 5;
        const float4* eg4 = (const float4*)ex_graph;
        int n0 = nh * 512 + ns * 64;
        float4 a = make_float4(0.f, 0.f, 0.f, 0.f);
        for (int t = 0; t < 64; t += 8) {
            float4 g[8]; float e[8];
            #pragma unroll
            for (int u = 0; u < 8; u++) {
                g[u] = eg4[(n0 + t + u) * 32 + j4];
                e[u] = sbuf[n0 + t + u];
            }
            #pragma unroll
            for (int u = 0; u < 8; u++) {
                a.x = fmaf(e[u], g[u].x, a.x);
                a.y = fmaf(e[u], g[u].y, a.y);
                a.z = fmaf(e[u], g[u].z, a.z);
                a.w = fmaf(e[u], g[u].w, a.w);
            }
        }
        __syncthreads();
        ((float4*)red)[ns * 32 + j4] = a;
        __syncthreads();
        if (tid < 128) {
            float s = 0.f;
            #pragma unroll
            for (int k = 0; k < 8; k++) s += red[k * 128 + tid];
            g_kci2[nh][b * 128 + tid] = s;
        }
    } else {
        // transposes for k2: twhhT (12288), WdhT (4096)
        int idx0 = (blk - 576) * 2048;
        for (int c = 0; c < 2048; c += 256) {
            int idx = idx0 + c + tid;                    // 0..16383
            if (idx < 12288) {
                int t = idx / 64, k = idx & 63;
                g_twhhT[k * 192 + t] = tgru_whh[idx];
            } else {
                int r = idx - 12288; int d = r >> 6, k = r & 63;
                g_WdhT[k * 64 + d] = fpart_w[d * 128 + k];
            }
        }
    }
}

// ---------------- K2: GRU compute + hidden k3-precompute blocks (R13) -------
__global__ void __launch_bounds__(256, 1) k2(
    const float* __restrict__ h,
    const float* __restrict__ tgru_wih,
    const float* __restrict__ tgru_bih,
    const float* __restrict__ tgru_bhh,
    const float* __restrict__ kc_gamma,
    const float* __restrict__ W_kc,
    const float* __restrict__ fpart_w, const float* __restrict__ fpart_b,
    const float* __restrict__ ulin_w,
    const float* __restrict__ ugru_wih, const float* __restrict__ ugru_whh)
{
    __shared__ __align__(16) float sraw[4160];
    int blk = blockIdx.x, tid = threadIdx.x;

    if (blk < 256) {
        float* x_s   = sraw;                        // 64
        float* git_s = sraw + 64;                   // 192
        float (*h_s)[64]     = (float(*)[64])(sraw + 256);
        float (*delta_s)[64] = (float(*)[64])(sraw + 1280);

        int row0 = blk * 16;
        int b = row0 >> 7;

        if (tid < 64) x_s[tid] = g_x[b * 64 + tid];
        ((float4*)h_s)[tid] = ((const float4*)(h + row0 * 64))[tid];
        __syncthreads();

        if (tid < 192) {
            const ulonglong2* wrow = (const ulonglong2*)(tgru_wih + tid * 64);
            const ulonglong2* xs2  = (const ulonglong2*)x_s;
            u64 a0 = 0ull, a1 = 0ull;
            #pragma unroll
            for (int i = 0; i < 16; i++) {
                ulonglong2 w = wrow[i];
                ulonglong2 xv = xs2[i];
                fma2(a0, w.x, xv.x);
                fma2(a1, w.y, xv.y);
            }
            float f0, f1, f2, f3;
            unpack2(a0, f0, f1); unpack2(a1, f2, f3);
            git_s[tid] = tgru_bih[tid] + ((f0 + f1) + (f2 + f3));
        }

        int l = tid >> 4, d4 = tid & 15;
        int row = row0 + l;
        ulonglong2 arp = ((const ulonglong2*)tgru_bhh)[d4];
        ulonglong2 azp = ((const ulonglong2*)tgru_bhh)[16 + d4];
        ulonglong2 anp = ((const ulonglong2*)tgru_bhh)[32 + d4];
        const ulonglong2* whh2 = (const ulonglong2*)g_twhhT;
        __syncthreads();

        #pragma unroll 8
        for (int k = 0; k < 64; k++) {
            float hk = h_s[l][k];
            u64 hp = pack2(hk, hk);
            ulonglong2 wr = whh2[k * 48 + d4];
            ulonglong2 wz = whh2[k * 48 + 16 + d4];
            ulonglong2 wn = whh2[k * 48 + 32 + d4];
            fma2(arp.x, wr.x, hp); fma2(arp.y, wr.y, hp);
            fma2(azp.x, wz.x, hp); fma2(azp.y, wz.y, hp);
            fma2(anp.x, wn.x, hp); fma2(anp.y, wn.y, hp);
        }
        float4 ar = up4(arp), az = up4(azp), an = up4(anp);

        float kciv = g_kci2[0][row] + g_kci2[1][row];
        float4 hv  = ((const float4*)h_s[l])[d4];
        float4 gir = ((const float4*)git_s)[d4];
        float4 giz = ((const float4*)git_s)[16 + d4];
        float4 gin = ((const float4*)git_s)[32 + d4];

        float4 nh4, dl4;
        {
            float r0 = sigf(gir.x + ar.x), z0 = sigf(giz.x + az.x);
            float n0 = tanhfast(gin.x + r0 * an.x);
            float th = (1.f - z0) * n0 + z0 * hv.x;
            dl4.x = kciv * (th - hv.x); nh4.x = hv.x + dl4.x;
        }
        {
            float r0 = sigf(gir.y + ar.y), z0 = sigf(giz.y + az.y);
            float n0 = tanhfast(gin.y + r0 * an.y);
            float th = (1.f - z0) * n0 + z0 * hv.y;
            dl4.y = kciv * (th - hv.y); nh4.y = hv.y + dl4.y;
        }
        {
            float r0 = sigf(gir.z + ar.z), z0 = sigf(giz.z + az.z);
            float n0 = tanhfast(gin.z + r0 * an.z);
            float th = (1.f - z0) * n0 + z0 * hv.z;
            dl4.z = kciv * (th - hv.z); nh4.z = hv.z + dl4.z;
        }
        {
            float r0 = sigf(gir.w + ar.w), z0 = sigf(giz.w + az.w);
            float n0 = tanhfast(gin.w + r0 * an.w);
            float th = (1.f - z0) * n0 + z0 * hv.w;
            dl4.w = kciv * (th - hv.w); nh4.w = hv.w + dl4.w;
        }
        ((float4*)(g_newh + row * 64))[d4] = nh4;
        ((float4*)delta_s[l])[d4] = dl4;
        __syncthreads();

        u64 ac01 = 0ull, ac23 = 0ull;
        const ulonglong2* wdh2 = (const ulonglong2*)g_WdhT;
        #pragma unroll 8
        for (int k = 0; k < 64; k++) {
            float dv = delta_s[l][k];
            u64 dp = pack2(dv, dv);
            ulonglong2 w = wdh2[k * 16 + d4];
            fma2(ac01, w.x, dp);
            fma2(ac23, w.y, dp);
        }
        float4 acc;
        unpack2(ac01, acc.x, acc.y); unpack2(ac23, acc.z, acc.w);
        ((float4*)(g_dpart + row * 64))[d4] = acc;
    } else if (blk < 264) {
        int base = (blk - 256) * 2048;
        for (int i = tid; i < 2048; i += 256)
            g_kcg[base + i] = sigf(kc_gamma[base + i]);
    } else if (blk < 296) {
        for (int i = tid; i < 64 * 64; i += 256) {
            int dd = i >> 6, k = i & 63;
            sraw[dd * 65 + k] = fpart_w[dd * 128 + 64 + k];
        }
        __syncthreads();
        int gid = (blk - 264) * 256 + tid;
        int j = gid >> 6, d = gid & 63;
        float acc = fpart_b[d];
        for (int t = 0; t < 64; t += 8) {
            float wv[8];
            #pragma unroll
            for (int u = 0; u < 8; u++) wv[u] = W_kc[(t + u) * 128 + j];
            #pragma unroll
            for (int u = 0; u < 8; u++) acc = fmaf(wv[u], sraw[d * 65 + t + u], acc);
        }
        g_epart[gid] = acc;
    } else {
        int idx0 = (blk - 296) * 3584;
        for (int c = 0; c < 3584; c += 256) {
            int idx = idx0 + c + tid;                    // 0..28671
            if (idx < 12288) {
                int t = idx / 64, k = idx & 63;
                g_uwihT[k * 192 + t] = ugru_wih[idx];
            } else if (idx < 24576) {
                int r = idx - 12288; int t = r / 64, k = r & 63;
                g_uwhhT[k * 192 + t] = ugru_whh[r];
            } else {
                int r = idx - 24576; int d = r >> 6, k = r & 63;
                g_ulinT[k * 64 + d] = ulin_w[r];
            }
        }
    }
}

// ---------------- K3: 512 threads, i-split partj + 1-j phase 2 --------------
// grid (4 jtiles, 32 b), 512 threads = (ihalf 0..1) x (jl 0..15) x (d4 0..15).
// Phase 1: each thread does 64 i for 2 j's; partials combined in smem.
// Phase 2: 1 j per thread (jl2 = tid>>4, 0..31).
__global__ void __launch_bounds__(512, 1) k3(
    const float* __restrict__ ugru_bih, const float* __restrict__ ugru_bhh,
    const float* __restrict__ ulin_b, float* __restrict__ out)
{
    __shared__ __align__(16) float sm[12288];        // 48KB
    // Region A: sm[0..8191]   phase1 dpart [128][16]f4; later pp/wk/newh/outj
    // Region B: sm[8192..12287] phase1 kcgw [128][32]; later partj (stride 72)
    float4* dpart4 = (float4*)sm;
    float*  kcgw   = sm + 8192;

    int jt = blockIdx.x, b = blockIdx.y;
    int tid = threadIdx.x;
    int ihalf = tid >> 8;            // 0..1
    int jl  = (tid >> 4) & 15;       // 0..15
    int d4  = tid & 15;              // 0..15
    int j0 = jt * 32 + jl, j1 = j0 + 16;

    const float4* dp4 = (const float4*)g_dpart + b * 2048;
    #pragma unroll
    for (int c = 0; c < 4; c++)
        dpart4[c * 512 + tid] = dp4[c * 512 + tid];
    #pragma unroll
    for (int c = 0; c < 8; c++) {
        int idx = c * 512 + tid;
        int ii = idx >> 5, jj = idx & 31;
        kcgw[idx] = g_kcg[ii * 128 + jt * 32 + jj]
                  * (g_kci2[0][b * 128 + ii] + g_kci2[1][b * 128 + ii]);
    }
    ulonglong2 epA = ((const ulonglong2*)g_epart)[j0 * 16 + d4];
    ulonglong2 epB = ((const ulonglong2*)g_epart)[j1 * 16 + d4];
    __syncthreads();

    // partj partials over this thread's i-half
    u64 acA0 = 0ull, acA1 = 0ull, acB0 = 0ull, acB1 = 0ull, wkp = 0ull;
    const ulonglong2* dp2 = (const ulonglong2*)sm;
    int i0 = ihalf * 64;
    #pragma unroll 4
    for (int i = i0; i < i0 + 64; i++) {
        ulonglong2 p = dp2[i * 16 + d4];
        float w0 = kcgw[i * 32 + jl];
        float w1 = kcgw[i * 32 + jl + 16];
        u64 w0p = pack2(w0, w0);
        u64 w1p = pack2(w1, w1);
        u64 t0 = add2(p.x, epA.x); u64 t1 = add2(p.y, epA.y);
        relu2(t0); relu2(t1);
        fma2(acA0, t0, w0p); fma2(acA1, t1, w0p);
        u64 s0 = add2(p.x, epB.x); u64 s1 = add2(p.y, epB.y);
        relu2(s0); relu2(s1);
        fma2(acB0, s0, w1p); fma2(acB1, s1, w1p);
        wkp = add2(wkp, pack2(w0, w1));
    }
    float4 a0, a1;
    unpack2(acA0, a0.x, a0.y); unpack2(acA1, a0.z, a0.w);
    unpack2(acB0, a1.x, a1.y); unpack2(acB1, a1.z, a1.w);
    float wk0p, wk1p;
    unpack2(wkp, wk0p, wk1p);
    __syncthreads();   // all reads of dpart/kcgw done; A reusable

    // write partials: pp [2][32][16]f4 at A[0..4095 floats]; wk at A[4096..4159]
    float4* pp4 = (float4*)sm;
    pp4[ihalf * 512 + jl * 16 + d4] = a0;
    pp4[ihalf * 512 + (jl + 16) * 16 + d4] = a1;
    if (d4 == 0) {
        sm[4096 + ihalf * 32 + jl]      = wk0p;
        sm[4096 + ihalf * 32 + jl + 16] = wk1p;
    }
    // stage newh [32][72] at A[4608..6911]
    {
        int row = tid >> 4, c4 = tid & 15;
        *(float4*)(sm + 4608 + row * 72 + c4 * 4) =
            ((const float4*)g_newh)[b * 2048 + jt * 512 + tid];
    }
    __syncthreads();

    // ---- phase 2: 1 j per thread ----
    int jl2 = tid >> 4;              // 0..31
    float* partj_sf = sm + 8192;     // [32][72]
    {
        float4 pa = pp4[jl2 * 16 + d4];
        float4 pb = pp4[512 + jl2 * 16 + d4];
        float4 s = make_float4(pa.x + pb.x, pa.y + pb.y, pa.z + pb.z, pa.w + pb.w);
        *(float4*)(partj_sf + jl2 * 72 + d4 * 4) = s;
    }
    float wk = sm[4096 + jl2] + sm[4096 + 32 + jl2];
    __syncthreads();

    // outj = relu(partj @ ulin_w.T + ulin_b)
    float* outj_s = sm;              // [32][72] at A[0..2303] (pp dead)
    {
        ulonglong2 op = ((const ulonglong2*)ulin_b)[d4];
        const ulonglong2* ul2 = (const ulonglong2*)g_ulinT;
        const float* prow = partj_sf + jl2 * 72;
        #pragma unroll 8
        for (int k = 0; k < 64; k++) {
            float p = prow[k];
            u64 q = pack2(p, p);
            ulonglong2 w = ul2[k * 16 + d4];
            fma2(op.x, w.x, q); fma2(op.y, w.y, q);
        }
        relu2(op.x); relu2(op.y);
        *(float4*)(outj_s + jl2 * 72 + d4 * 4) = up4(op);
    }
    __syncthreads();

    // u-GRU: 1 j per thread, 12 FFMA2/k
    ulonglong2 grp = ((const ulonglong2*)ugru_bih)[d4];
    ulonglong2 gzp = ((const ulonglong2*)ugru_bih)[16 + d4];
    ulonglong2 gnp = ((const ulonglong2*)ugru_bih)[32 + d4];
    ulonglong2 hrp = ((const ulonglong2*)ugru_bhh)[d4];
    ulonglong2 hzp = ((const ulonglong2*)ugru_bhh)[16 + d4];
    ulonglong2 hnp = ((const ulonglong2*)ugru_bhh)[32 + d4];
    const ulonglong2* wih2 = (const ulonglong2*)g_uwihT;
    const ulonglong2* whh2 = (const ulonglong2*)g_uwhhT;
    const float* orow = outj_s + jl2 * 72;
    const float* nrow = sm + 4608 + jl2 * 72;
    #pragma unroll 4
    for (int k = 0; k < 64; k++) {
        float ok = orow[k], nk = nrow[k];
        u64 O = pack2(ok, ok), N = pack2(nk, nk);
        ulonglong2 wr = wih2[k * 48 + d4];
        ulonglong2 wz = wih2[k * 48 + 16 + d4];
        ulonglong2 wn = wih2[k * 48 + 32 + d4];
        ulonglong2 vr = whh2[k * 48 + d4];
        ulonglong2 vz = whh2[k * 48 + 16 + d4];
        ulonglong2 vn = whh2[k * 48 + 32 + d4];
        fma2(grp.x, wr.x, O); fma2(grp.y, wr.y, O);
        fma2(gzp.x, wz.x, O); fma2(gzp.y, wz.y, O);
        fma2(gnp.x, wn.x, O); fma2(gnp.y, wn.y, O);
        fma2(hrp.x, vr.x, N); fma2(hrp.y, vr.y, N);
        fma2(hzp.x, vz.x, N); fma2(hzp.y, vz.y, N);
        fma2(hnp.x, vn.x, N); fma2(hnp.y, vn.y, N);
    }
    float4 gr = up4(grp), gz = up4(gzp), gn = up4(gnp);
    float4 hr = up4(hrp), hz = up4(hzp), hn = up4(hnp);

    float4 nh4 = *(const float4*)(nrow + d4 * 4);
    float4 res;
    {
        float r = sigf(gr.x + hr.x), z = sigf(gz.x + hz.x);
        float n = tanhfast(gn.x + r * hn.x);
        float uh = (1.f - z) * n + z * nh4.x;
        res.x = nh4.x + wk * (uh - nh4.x);
    }
    {
        float r = sigf(gr.y + hr.y), z = sigf(gz.y + hz.y);
        float n = tanhfast(gn.y + r * hn.y);
        float uh = (1.f - z) * n + z * nh4.y;
        res.y = nh4.y + wk * (uh - nh4.y);
    }
    {
        float r = sigf(gr.z + hr.z), z = sigf(gz.z + hz.z);
        float n = tanhfast(gn.z + r * hn.z);
        float uh = (1.f - z) * n + z * nh4.z;
        res.z = nh4.z + wk * (uh - nh4.z);
    }
    {
        float r = sigf(gr.w + hr.w), z = sigf(gz.w + hz.w);
        float n = tanhfast(gn.w + r * hn.w);
        float uh = (1.f - z) * n + z * nh4.w;
        res.w = nh4.w + wk * (uh - nh4.w);
    }
    ((float4*)out)[(b * 128 + jt * 32 + jl2) * 16 + d4] = res;
}

// ---------------- launch ----------------------------------------------------
extern "C" void kernel_launch(void* const* d_in, const int* in_sizes, int n_in,
                              void* d_out, int out_size)
{
    const float* h        = (const float*)d_in[0];
    const float* ex       = (const float*)d_in[1];
    const float* su       = (const float*)d_in[2];
    const float* ex_graph = (const float*)d_in[3];
    const float* kc_gamma = (const float*)d_in[4];
    const float* W_ex     = (const float*)d_in[5];
    const float* W_kc     = (const float*)d_in[6];
    const float* tgru_wih = (const float*)d_in[7];
    const float* tgru_whh = (const float*)d_in[8];
    const float* tgru_bih = (const float*)d_in[9];
    const float* tgru_bhh = (const float*)d_in[10];
    const float* fpart_w  = (const float*)d_in[11];
    const float* fpart_b  = (const float*)d_in[12];
    const float* ulin_w   = (const float*)d_in[13];
    const float* ulin_b   = (const float*)d_in[14];
    const float* ugru_wih = (const float*)d_in[15];
    const float* ugru_whh = (const float*)d_in[16];
    const float* ugru_bih = (const float*)d_in[17];
    const float* ugru_bhh = (const float*)d_in[18];
    float* out = (float*)d_out;

    k0<<<584, 256>>>(ex, su, ex_graph, W_ex, tgru_whh, fpart_w);
    k2<<<304, 256>>>(h, tgru_wih, tgru_bih, tgru_bhh, kc_gamma, W_kc,
                     fpart_w, fpart_b, ulin_w, ugru_wih, ugru_whh);
    dim3 g3(4, 32);
    k3<<<g3, 512>>>(ugru_bih, ugru_bhh, ulin_b, out);
}

// round 17
// speedup vs baseline: 1.0879x; 1.0879x over previous
#include <cuda_runtime.h>
#include <cuda_bf16.h>

#define BB   32
#define NEX  1024
#define NKC  128
#define DH   64

typedef unsigned long long u64;

// ---------------- scratch (device globals, 16B-aligned) --------------------
__device__ __align__(16) float g_x[BB * 64];
__device__ __align__(16) float g_kci2[2][BB * NKC];   // two n-half partials
__device__ __align__(16) float g_kcg[NKC * NKC];
__device__ __align__(16) float g_epart[NKC * 64];
__device__ __align__(16) float g_newh[BB * NKC * 64];
__device__ __align__(16) float g_dpart[BB * NKC * 64];
__device__ __align__(16) float g_twhhT[64 * 192];
__device__ __align__(16) float g_WdhT[64 * 64];
__device__ __align__(16) float g_ulinT[64 * 64];
__device__ __align__(16) float g_uwihT[64 * 192];
__device__ __align__(16) float g_uwhhT[64 * 192];

__device__ __forceinline__ float sigf(float v)     { return 1.f / (1.f + __expf(-v)); }
__device__ __forceinline__ float tanhfast(float v) { return 2.f / (1.f + __expf(-2.f * v)) - 1.f; }

// packed f32x2 helpers (FFMA2: 2 fp32 lanes per issue slot)
__device__ __forceinline__ u64 pack2(float x, float y) {
    u64 r; asm("mov.b64 %0, {%1, %2};" : "=l"(r) : "f"(x), "f"(y)); return r;
}
__device__ __forceinline__ void fma2(u64& acc, u64 a, u64 b) {
    asm("fma.rn.f32x2 %0, %1, %2, %0;" : "+l"(acc) : "l"(a), "l"(b));
}
__device__ __forceinline__ u64 add2(u64 a, u64 b) {
    u64 r; asm("add.rn.f32x2 %0, %1, %2;" : "=l"(r) : "l"(a), "l"(b)); return r;
}
// relu on both halves of a packed pair (scalar max.f32 on halves; movs elide)
__device__ __forceinline__ void relu2(u64& v) {
    asm("{ .reg .f32 lo, hi;\n\t"
        "mov.b64 {lo, hi}, %0;\n\t"
        "max.f32 lo, lo, 0f00000000;\n\t"
        "max.f32 hi, hi, 0f00000000;\n\t"
        "mov.b64 %0, {lo, hi}; }" : "+l"(v));
}
__device__ __forceinline__ void unpack2(u64 v, float& x, float& y) {
    asm("mov.b64 {%0, %1}, %2;" : "=f"(x), "=f"(y) : "l"(v));
}
__device__ __forceinline__ float4 up4(ulonglong2 v) {
    float4 f; unpack2(v.x, f.x, f.y); unpack2(v.y, f.z, f.w); return f;
}

// ---------------- K0: only what K2 needs, 584 blocks x 256 (R13 layout) -----
// blocks   0..511 : x      (2 warps per output, 12-load chains)
// blocks 512..575 : kci    (2 blocks per b, 8-deep load batching)
// blocks 576..583 : transposes twhhT, WdhT (16384 elems)
__global__ void __launch_bounds__(256, 1) k0(
    const float* __restrict__ ex, const float* __restrict__ su,
    const float* __restrict__ ex_graph,
    const float* __restrict__ W_ex,
    const float* __restrict__ tgru_whh,
    const float* __restrict__ fpart_w)
{
    __shared__ __align__(16) float sbuf[2176];
    int blk = blockIdx.x, tid = threadIdx.x;

    if (blk < 512) {
        int w = tid >> 5, lane = tid & 31;
        int oid = blk * 4 + (w >> 1);          // 0..2047
        int half = w & 1;
        int b = oid >> 6, e = oid & 63;
        const float4* W4  = (const float4*)W_ex + e * 512 + half * 128;
        const float4* ex4 = (const float4*)ex + b * 256 + half * 128;
        float4 ev[4], wa[4], wb[4];
        #pragma unroll
        for (int i = 0; i < 4; i++) {
            int idx = i * 32 + lane;
            ev[i] = ex4[idx];
            wa[i] = W4[idx];
            wb[i] = W4[256 + idx];
        }
        float a1 = 0.f, a2 = 0.f;
        #pragma unroll
        for (int i = 0; i < 4; i++) {
            a1 = fmaf(ev[i].x, wa[i].x, fmaf(ev[i].y, wa[i].y, fmaf(ev[i].z, wa[i].z, fmaf(ev[i].w, wa[i].w, a1))));
            a2 = fmaf(ev[i].x, wb[i].x, fmaf(ev[i].y, wb[i].y, fmaf(ev[i].z, wb[i].z, fmaf(ev[i].w, wb[i].w, a2))));
        }
        #pragma unroll
        for (int o = 16; o; o >>= 1) {
            a1 += __shfl_xor_sync(0xffffffffu, a1, o);
            a2 += __shfl_xor_sync(0xffffffffu, a2, o);
        }
        if (lane == 0) { sbuf[w * 2] = a1; sbuf[w * 2 + 1] = a2; }
        __syncthreads();
        if (tid < 4) {
            int o2 = blk * 4 + tid;
            float s1 = sbuf[tid * 4] + sbuf[tid * 4 + 2];
            float s2 = sbuf[tid * 4 + 1] + sbuf[tid * 4 + 3];
            float s = su[o2 >> 6];
            g_x[o2] = s * s1 + (1.f - s) * s2;
        }
    } else if (blk < 576) {
        int idx = blk - 512;
        int b = idx >> 1, nh = idx & 1;
        float4* exs4 = (float4*)sbuf;
        float*  red  = sbuf + 1024;
        exs4[tid] = ((const float4*)ex)[b * 256 + tid];
        __syncthreads();
        int j4 = tid & 31, ns = tid >> 5;
        const float4* eg4 = (const float4*)ex_graph;
        int n0 = nh * 512 + ns * 64;
        float4 a = make_float4(0.f, 0.f, 0.f, 0.f);
        for (int t = 0; t < 64; t += 8) {
            float4 g[8]; float e[8];
            #pragma unroll
            for (int u = 0; u < 8; u++) {
                g[u] = eg4[(n0 + t + u) * 32 + j4];
                e[u] = sbuf[n0 + t + u];
            }
            #pragma unroll
            for (int u = 0; u < 8; u++) {
                a.x = fmaf(e[u], g[u].x, a.x);
                a.y = fmaf(e[u], g[u].y, a.y);
                a.z = fmaf(e[u], g[u].z, a.z);
                a.w = fmaf(e[u], g[u].w, a.w);
            }
        }
        __syncthreads();
        ((float4*)red)[ns * 32 + j4] = a;
        __syncthreads();
        if (tid < 128) {
            float s = 0.f;
            #pragma unroll
            for (int k = 0; k < 8; k++) s += red[k * 128 + tid];
            g_kci2[nh][b * 128 + tid] = s;
        }
    } else {
        // transposes for k2: twhhT (12288), WdhT (4096)
        int idx0 = (blk - 576) * 2048;
        for (int c = 0; c < 2048; c += 256) {
            int idx = idx0 + c + tid;                    // 0..16383
            if (idx < 12288) {
                int t = idx / 64, k = idx & 63;
                g_twhhT[k * 192 + t] = tgru_whh[idx];
            } else {
                int r = idx - 12288; int d = r >> 6, k = r & 63;
                g_WdhT[k * 64 + d] = fpart_w[d * 128 + k];
            }
        }
    }
}

// ---------------- K2: GRU compute + hidden k3-precompute blocks (R13) -------
__global__ void __launch_bounds__(256, 1) k2(
    const float* __restrict__ h,
    const float* __restrict__ tgru_wih,
    const float* __restrict__ tgru_bih,
    const float* __restrict__ tgru_bhh,
    const float* __restrict__ kc_gamma,
    const float* __restrict__ W_kc,
    const float* __restrict__ fpart_w, const float* __restrict__ fpart_b,
    const float* __restrict__ ulin_w,
    const float* __restrict__ ugru_wih, const float* __restrict__ ugru_whh)
{
    __shared__ __align__(16) float sraw[4160];
    int blk = blockIdx.x, tid = threadIdx.x;

    if (blk < 256) {
        float* x_s   = sraw;                        // 64
        float* git_s = sraw + 64;                   // 192
        float (*h_s)[64]     = (float(*)[64])(sraw + 256);
        float (*delta_s)[64] = (float(*)[64])(sraw + 1280);

        int row0 = blk * 16;
        int b = row0 >> 7;

        if (tid < 64) x_s[tid] = g_x[b * 64 + tid];
        ((float4*)h_s)[tid] = ((const float4*)(h + row0 * 64))[tid];
        __syncthreads();

        if (tid < 192) {
            const ulonglong2* wrow = (const ulonglong2*)(tgru_wih + tid * 64);
            const ulonglong2* xs2  = (const ulonglong2*)x_s;
            u64 a0 = 0ull, a1 = 0ull;
            #pragma unroll
            for (int i = 0; i < 16; i++) {
                ulonglong2 w = wrow[i];
                ulonglong2 xv = xs2[i];
                fma2(a0, w.x, xv.x);
                fma2(a1, w.y, xv.y);
            }
            float f0, f1, f2, f3;
            unpack2(a0, f0, f1); unpack2(a1, f2, f3);
            git_s[tid] = tgru_bih[tid] + ((f0 + f1) + (f2 + f3));
        }

        int l = tid >> 4, d4 = tid & 15;
        int row = row0 + l;
        ulonglong2 arp = ((const ulonglong2*)tgru_bhh)[d4];
        ulonglong2 azp = ((const ulonglong2*)tgru_bhh)[16 + d4];
        ulonglong2 anp = ((const ulonglong2*)tgru_bhh)[32 + d4];
        const ulonglong2* whh2 = (const ulonglong2*)g_twhhT;
        __syncthreads();

        #pragma unroll 8
        for (int k = 0; k < 64; k++) {
            float hk = h_s[l][k];
            u64 hp = pack2(hk, hk);
            ulonglong2 wr = whh2[k * 48 + d4];
            ulonglong2 wz = whh2[k * 48 + 16 + d4];
            ulonglong2 wn = whh2[k * 48 + 32 + d4];
            fma2(arp.x, wr.x, hp); fma2(arp.y, wr.y, hp);
            fma2(azp.x, wz.x, hp); fma2(azp.y, wz.y, hp);
            fma2(anp.x, wn.x, hp); fma2(anp.y, wn.y, hp);
        }
        float4 ar = up4(arp), az = up4(azp), an = up4(anp);

        float kciv = g_kci2[0][row] + g_kci2[1][row];
        float4 hv  = ((const float4*)h_s[l])[d4];
        float4 gir = ((const float4*)git_s)[d4];
        float4 giz = ((const float4*)git_s)[16 + d4];
        float4 gin = ((const float4*)git_s)[32 + d4];

        float4 nh4, dl4;
        {
            float r0 = sigf(gir.x + ar.x), z0 = sigf(giz.x + az.x);
            float n0 = tanhfast(gin.x + r0 * an.x);
            float th = (1.f - z0) * n0 + z0 * hv.x;
            dl4.x = kciv * (th - hv.x); nh4.x = hv.x + dl4.x;
        }
        {
            float r0 = sigf(gir.y + ar.y), z0 = sigf(giz.y + az.y);
            float n0 = tanhfast(gin.y + r0 * an.y);
            float th = (1.f - z0) * n0 + z0 * hv.y;
            dl4.y = kciv * (th - hv.y); nh4.y = hv.y + dl4.y;
        }
        {
            float r0 = sigf(gir.z + ar.z), z0 = sigf(giz.z + az.z);
            float n0 = tanhfast(gin.z + r0 * an.z);
            float th = (1.f - z0) * n0 + z0 * hv.z;
            dl4.z = kciv * (th - hv.z); nh4.z = hv.z + dl4.z;
        }
        {
            float r0 = sigf(gir.w + ar.w), z0 = sigf(giz.w + az.w);
            float n0 = tanhfast(gin.w + r0 * an.w);
            float th = (1.f - z0) * n0 + z0 * hv.w;
            dl4.w = kciv * (th - hv.w); nh4.w = hv.w + dl4.w;
        }
        ((float4*)(g_newh + row * 64))[d4] = nh4;
        ((float4*)delta_s[l])[d4] = dl4;
        __syncthreads();

        u64 ac01 = 0ull, ac23 = 0ull;
        const ulonglong2* wdh2 = (const ulonglong2*)g_WdhT;
        #pragma unroll 8
        for (int k = 0; k < 64; k++) {
            float dv = delta_s[l][k];
            u64 dp = pack2(dv, dv);
            ulonglong2 w = wdh2[k * 16 + d4];
            fma2(ac01, w.x, dp);
            fma2(ac23, w.y, dp);
        }
        float4 acc;
        unpack2(ac01, acc.x, acc.y); unpack2(ac23, acc.z, acc.w);
        ((float4*)(g_dpart + row * 64))[d4] = acc;
    } else if (blk < 264) {
        int base = (blk - 256) * 2048;
        for (int i = tid; i < 2048; i += 256)
            g_kcg[base + i] = sigf(kc_gamma[base + i]);
    } else if (blk < 296) {
        for (int i = tid; i < 64 * 64; i += 256) {
            int dd = i >> 6, k = i & 63;
            sraw[dd * 65 + k] = fpart_w[dd * 128 + 64 + k];
        }
        __syncthreads();
        int gid = (blk - 264) * 256 + tid;
        int j = gid >> 6, d = gid & 63;
        float acc = fpart_b[d];
        for (int t = 0; t < 64; t += 8) {
            float wv[8];
            #pragma unroll
            for (int u = 0; u < 8; u++) wv[u] = W_kc[(t + u) * 128 + j];
            #pragma unroll
            for (int u = 0; u < 8; u++) acc = fmaf(wv[u], sraw[d * 65 + t + u], acc);
        }
        g_epart[gid] = acc;
    } else {
        int idx0 = (blk - 296) * 3584;
        for (int c = 0; c < 3584; c += 256) {
            int idx = idx0 + c + tid;                    // 0..28671
            if (idx < 12288) {
                int t = idx / 64, k = idx & 63;
                g_uwihT[k * 192 + t] = ugru_wih[idx];
            } else if (idx < 24576) {
                int r = idx - 12288; int t = r / 64, k = r & 63;
                g_uwhhT[k * 192 + t] = ugru_whh[r];
            } else {
                int r = idx - 24576; int d = r >> 6, k = r & 63;
                g_ulinT[k * 64 + d] = ulin_w[r];
            }
        }
    }
}

// ---------------- K3: broadcast-layout partj + R13 phase 2 ------------------
// grid (4 jtiles, 32 b), 256 threads.
// Phase 1: thread = (j 0..31, dg 0..7); warp = 32 j at fixed dg -> dpart LDS
//          is single-address broadcast (1 wf), kcgw conflict-free.
// Phase 2: R13 mapping (jl 0..15, d4 0..15; 2 j per thread), stride 68.
__global__ void __launch_bounds__(256, 1) k3(
    const float* __restrict__ ugru_bih, const float* __restrict__ ugru_bhh,
    const float* __restrict__ ulin_b, float* __restrict__ out)
{
    __shared__ __align__(16) float sm[12288];        // 48KB
    // phase 1: dpart [128][16]f4 at 0..8191; kcgw [128][32] at 8192..12287
    // phase 2: partj [32][68] at 0; outj [32][68] at 2560; newh [32][68] at 5120
    //          wk [32] at 8192 (kcgw dead)
    float4* dpart4 = (float4*)sm;
    float*  kcgw   = sm + 8192;

    int jt = blockIdx.x, b = blockIdx.y;
    int tid = threadIdx.x;

    const float4* dp4 = (const float4*)g_dpart + b * 2048;
    #pragma unroll
    for (int c = 0; c < 8; c++)
        dpart4[c * 256 + tid] = dp4[c * 256 + tid];
    #pragma unroll
    for (int c = 0; c < 16; c++) {
        int idx = c * 256 + tid;
        int ii = idx >> 5, jj = idx & 31;
        kcgw[idx] = g_kcg[ii * 128 + jt * 32 + jj]
                  * (g_kci2[0][b * 128 + ii] + g_kci2[1][b * 128 + ii]);
    }

    // phase-1 mapping: j = tid&31, dg = tid>>5 (warp id); d = dg*8..dg*8+7
    int j = tid & 31, dg = tid >> 5;
    int jg = jt * 32 + j;
    ulonglong2 ep0 = ((const ulonglong2*)g_epart)[jg * 16 + dg * 2];
    ulonglong2 ep1 = ((const ulonglong2*)g_epart)[jg * 16 + dg * 2 + 1];
    __syncthreads();

    u64 ac0 = 0ull, ac1 = 0ull, ac2 = 0ull, ac3 = 0ull;
    float wk = 0.f;
    const ulonglong2* dp2 = (const ulonglong2*)sm;
    #pragma unroll 4
    for (int i = 0; i < NKC; i++) {
        ulonglong2 p0 = dp2[i * 16 + dg * 2];        // broadcast within warp
        ulonglong2 p1 = dp2[i * 16 + dg * 2 + 1];    // broadcast within warp
        float w = kcgw[i * 32 + j];                  // conflict-free
        u64 wp = pack2(w, w);
        u64 t0 = add2(p0.x, ep0.x); relu2(t0); fma2(ac0, t0, wp);
        u64 t1 = add2(p0.y, ep0.y); relu2(t1); fma2(ac1, t1, wp);
        u64 t2 = add2(p1.x, ep1.x); relu2(t2); fma2(ac2, t2, wp);
        u64 t3 = add2(p1.y, ep1.y); relu2(t3); fma2(ac3, t3, wp);
        wk += w;
    }
    ulonglong2 ra, rb;
    ra.x = ac0; ra.y = ac1; rb.x = ac2; rb.y = ac3;
    float4 r0 = up4(ra), r1 = up4(rb);
    __syncthreads();   // dpart/kcgw regions now dead

    // partj [32][68] at sm+0
    *(float4*)(sm + j * 68 + dg * 8)     = r0;
    *(float4*)(sm + j * 68 + dg * 8 + 4) = r1;
    if (dg == 0) sm[8192 + j] = wk;      // wk per j (identical across dg)
    // stage newh [32][68] at sm+5120
    {
        #pragma unroll
        for (int c = 0; c < 2; c++) {
            int idx = c * 256 + tid;
            int row = idx >> 4, c4 = idx & 15;
            *(float4*)(sm + 5120 + row * 68 + c4 * 4) =
                ((const float4*)g_newh)[b * 2048 + jt * 512 + idx];
        }
    }
    __syncthreads();

    // ---- phase 2 (R13): jl 0..15, d4 0..15; thread owns jl and jl+16 ----
    int jl = tid >> 4, d4 = tid & 15;
    float wk0 = sm[8192 + jl];
    float wk1 = sm[8192 + jl + 16];

    // outj = relu(partj @ ulin_w.T + ulin_b)
    {
        ulonglong2 ob = ((const ulonglong2*)ulin_b)[d4];
        ulonglong2 o0p = ob, o1p = ob;
        const ulonglong2* ul2 = (const ulonglong2*)g_ulinT;
        const float* p0row = sm + jl * 68;
        const float* p1row = sm + (jl + 16) * 68;
        #pragma unroll 8
        for (int k = 0; k < 64; k++) {
            float p0 = p0row[k];
            float p1 = p1row[k];
            u64 q0 = pack2(p0, p0);
            u64 q1 = pack2(p1, p1);
            ulonglong2 w = ul2[k * 16 + d4];
            fma2(o0p.x, w.x, q0); fma2(o0p.y, w.y, q0);
            fma2(o1p.x, w.x, q1); fma2(o1p.y, w.y, q1);
        }
        relu2(o0p.x); relu2(o0p.y);
        relu2(o1p.x); relu2(o1p.y);
        *(float4*)(sm + 2560 + jl * 68 + d4 * 4)        = up4(o0p);
        *(float4*)(sm + 2560 + (jl + 16) * 68 + d4 * 4) = up4(o1p);
    }
    __syncthreads();

    // u-GRU (packed f32x2)
    ulonglong2 bihr = ((const ulonglong2*)ugru_bih)[d4];
    ulonglong2 bihz = ((const ulonglong2*)ugru_bih)[16 + d4];
    ulonglong2 bihn = ((const ulonglong2*)ugru_bih)[32 + d4];
    ulonglong2 bhhr = ((const ulonglong2*)ugru_bhh)[d4];
    ulonglong2 bhhz = ((const ulonglong2*)ugru_bhh)[16 + d4];
    ulonglong2 bhhn = ((const ulonglong2*)ugru_bhh)[32 + d4];
    ulonglong2 gr0p = bihr, gz0p = bihz, gn0p = bihn;
    ulonglong2 hr0p = bhhr, hz0p = bhhz, hn0p = bhhn;
    ulonglong2 gr1p = bihr, gz1p = bihz, gn1p = bihn;
    ulonglong2 hr1p = bhhr, hz1p = bhhz, hn1p = bhhn;
    const ulonglong2* wih2 = (const ulonglong2*)g_uwihT;
    const ulonglong2* whh2 = (const ulonglong2*)g_uwhhT;
    const float* o0row = sm + 2560 + jl * 68;
    const float* o1row = sm + 2560 + (jl + 16) * 68;
    const float* n0row = sm + 5120 + jl * 68;
    const float* n1row = sm + 5120 + (jl + 16) * 68;
    #pragma unroll 4
    for (int k = 0; k < 64; k++) {
        float ok0 = o0row[k], ok1 = o1row[k];
        float nk0 = n0row[k], nk1 = n1row[k];
        u64 O0 = pack2(ok0, ok0), O1 = pack2(ok1, ok1);
        u64 N0 = pack2(nk0, nk0), N1 = pack2(nk1, nk1);
        ulonglong2 wr = wih2[k * 48 + d4];
        ulonglong2 wz = wih2[k * 48 + 16 + d4];
        ulonglong2 wn = wih2[k * 48 + 32 + d4];
        ulonglong2 vr = whh2[k * 48 + d4];
        ulonglong2 vz = whh2[k * 48 + 16 + d4];
        ulonglong2 vn = whh2[k * 48 + 32 + d4];
        fma2(gr0p.x, wr.x, O0); fma2(gr0p.y, wr.y, O0);
        fma2(gz0p.x, wz.x, O0); fma2(gz0p.y, wz.y, O0);
        fma2(gn0p.x, wn.x, O0); fma2(gn0p.y, wn.y, O0);
        fma2(hr0p.x, vr.x, N0); fma2(hr0p.y, vr.y, N0);
        fma2(hz0p.x, vz.x, N0); fma2(hz0p.y, vz.y, N0);
        fma2(hn0p.x, vn.x, N0); fma2(hn0p.y, vn.y, N0);
        fma2(gr1p.x, wr.x, O1); fma2(gr1p.y, wr.y, O1);
        fma2(gz1p.x, wz.x, O1); fma2(gz1p.y, wz.y, O1);
        fma2(gn1p.x, wn.x, O1); fma2(gn1p.y, wn.y, O1);
        fma2(hr1p.x, vr.x, N1); fma2(hr1p.y, vr.y, N1);
        fma2(hz1p.x, vz.x, N1); fma2(hz1p.y, vz.y, N1);
        fma2(hn1p.x, vn.x, N1); fma2(hn1p.y, vn.y, N1);
    }
    float4 gr0 = up4(gr0p), gz0 = up4(gz0p), gn0 = up4(gn0p);
    float4 hr0 = up4(hr0p), hz0 = up4(hz0p), hn0 = up4(hn0p);
    float4 gr1 = up4(gr1p), gz1 = up4(gz1p), gn1 = up4(gn1p);
    float4 hr1 = up4(hr1p), hz1 = up4(hz1p), hn1 = up4(hn1p);

    float4 nha = *(const float4*)(n0row + d4 * 4);
    float4 nhb = *(const float4*)(n1row + d4 * 4);
    float4 res0, res1;
    {
        float r = sigf(gr0.x + hr0.x), z = sigf(gz0.x + hz0.x);
        float n = tanhfast(gn0.x + r * hn0.x);
        float uh = (1.f - z) * n + z * nha.x;
        res0.x = nha.x + wk0 * (uh - nha.x);
    }
    {
        float r = sigf(gr0.y + hr0.y), z = sigf(gz0.y + hz0.y);
        float n = tanhfast(gn0.y + r * hn0.y);
        float uh = (1.f - z) * n + z * nha.y;
        res0.y = nha.y + wk0 * (uh - nha.y);
    }
    {
        float r = sigf(gr0.z + hr0.z), z = sigf(gz0.z + hz0.z);
        float n = tanhfast(gn0.z + r * hn0.z);
        float uh = (1.f - z) * n + z * nha.z;
        res0.z = nha.z + wk0 * (uh - nha.z);
    }
    {
        float r = sigf(gr0.w + hr0.w), z = sigf(gz0.w + hz0.w);
        float n = tanhfast(gn0.w + r * hn0.w);
        float uh = (1.f - z) * n + z * nha.w;
        res0.w = nha.w + wk0 * (uh - nha.w);
    }
    {
        float r = sigf(gr1.x + hr1.x), z = sigf(gz1.x + hz1.x);
        float n = tanhfast(gn1.x + r * hn1.x);
        float uh = (1.f - z) * n + z * nhb.x;
        res1.x = nhb.x + wk1 * (uh - nhb.x);
    }
    {
        float r = sigf(gr1.y + hr1.y), z = sigf(gz1.y + hz1.y);
        float n = tanhfast(gn1.y + r * hn1.y);
        float uh = (1.f - z) * n + z * nhb.y;
        res1.y = nhb.y + wk1 * (uh - nhb.y);
    }
    {
        float r = sigf(gr1.z + hr1.z), z = sigf(gz1.z + hz1.z);
        float n = tanhfast(gn1.z + r * hn1.z);
        float uh = (1.f - z) * n + z * nhb.z;
        res1.z = nhb.z + wk1 * (uh - nhb.z);
    }
    {
        float r = sigf(gr1.w + hr1.w), z = sigf(gz1.w + hz1.w);
        float n = tanhfast(gn1.w + r * hn1.w);
        float uh = (1.f - z) * n + z * nhb.w;
        res1.w = nhb.w + wk1 * (uh - nhb.w);
    }
    ((float4*)out)[(b * 128 + jt * 32 + jl) * 16 + d4]      = res0;
    ((float4*)out)[(b * 128 + jt * 32 + jl + 16) * 16 + d4] = res1;
}

// ---------------- launch ----------------------------------------------------
extern "C" void kernel_launch(void* const* d_in, const int* in_sizes, int n_in,
                              void* d_out, int out_size)
{
    const float* h        = (const float*)d_in[0];
    const float* ex       = (const float*)d_in[1];
    const float* su       = (const float*)d_in[2];
    const float* ex_graph = (const float*)d_in[3];
    const float* kc_gamma = (const float*)d_in[4];
    const float* W_ex     = (const float*)d_in[5];
    const float* W_kc     = (const float*)d_in[6];
    const float* tgru_wih = (const float*)d_in[7];
    const float* tgru_whh = (const float*)d_in[8];
    const float* tgru_bih = (const float*)d_in[9];
    const float* tgru_bhh = (const float*)d_in[10];
    const float* fpart_w  = (const float*)d_in[11];
    const float* fpart_b  = (const float*)d_in[12];
    const float* ulin_w   = (const float*)d_in[13];
    const float* ulin_b   = (const float*)d_in[14];
    const float* ugru_wih = (const float*)d_in[15];
    const float* ugru_whh = (const float*)d_in[16];
    const float* ugru_bih = (const float*)d_in[17];
    const float* ugru_bhh = (const float*)d_in[18];
    float* out = (float*)d_out;

    k0<<<584, 256>>>(ex, su, ex_graph, W_ex, tgru_whh, fpart_w);
    k2<<<304, 256>>>(h, tgru_wih, tgru_bih, tgru_bhh, kc_gamma, W_kc,
                     fpart_w, fpart_b, ulin_w, ugru_wih, ugru_whh);
    dim3 g3(4, 32);
    k3<<<g3, 256>>>(ugru_bih, ugru_bhh, ulin_b, out);
}